// round 1
// baseline (speedup 1.0000x reference)
#include <cuda_runtime.h>

#define N_NODES 100000
#define N_EDGES 1600000
#define IN_DIM  256
#define OUT_DIM 128
#define BATCH   8192
#define CAP     192
#define SLOPE   0.1f
#define EPS     1e-8f

// ---------------- static device scratch (no runtime allocation) ----------------
__device__ int   g_is64;                 // 1 if index arrays are int64, 0 if int32
__device__ float g_v1[IN_DIM];           // W @ a[:128]
__device__ float g_v2[IN_DIM];           // W @ a[128:]
__device__ float g_c1, g_c2;             // b.a[:128], b.a[128:]
__device__ int   g_slot[N_NODES];        // node -> representative batch slot (INT_MAX if unmarked)
__device__ int   g_cnt[BATCH];           // edges bucketed per slot
__device__ float g_ssrc[BATCH];          // s_src per batch position (incl. c1)
__device__ int   g_gc[BATCH * CAP];      // bucketed c-endpoints per slot
__device__ __align__(16) float g_agg[BATCH * IN_DIM];     // sum_e w_e * feats[c_e]
__device__ float g_denom[BATCH];
__device__ __align__(16) float g_outrow[BATCH * OUT_DIM]; // per-slot final rows

__device__ __forceinline__ int load_idx(const void* p, int i, int is64) {
    if (is64) return (int)((const long long*)p)[i];
    return ((const int*)p)[i];
}

// ---------------- K_detect: runtime int32/int64 detection on r ----------------
__global__ void k_detect(const void* __restrict__ rp) {
    // Sample the first half of the buffer interpreted as int64 (safe for both dtypes).
    const long long* r64 = (const long long*)rp;
    const int stride = (N_EDGES / 2) / 64;   // 12500
    int ok = 1;
    for (int i = 0; i < 64; i++) {
        long long v = r64[(long long)i * stride];
        if (v < 0 || v >= N_NODES) { ok = 0; break; }
    }
    g_is64 = ok;   // int32 pairs would read as huge int64s (P(miss) ~ (1e-5)^64)
}

// ---------------- K_prep: v1 = W@a1, v2 = W@a2, c1 = b.a1, c2 = b.a2 ----------------
__global__ void k_prep(const float* __restrict__ W, const float* __restrict__ b,
                       const float* __restrict__ a) {
    int k = threadIdx.x;                 // 256 threads
    const float* wrow = W + k * OUT_DIM;
    float s1 = 0.f, s2 = 0.f;
    for (int j = 0; j < OUT_DIM; j++) {
        float w = wrow[j];
        s1 += w * a[j];
        s2 += w * a[OUT_DIM + j];
    }
    g_v1[k] = s1;
    g_v2[k] = s2;

    __shared__ float sb1[OUT_DIM], sb2[OUT_DIM];
    if (k < OUT_DIM) {
        float bb = b[k];
        sb1[k] = bb * a[k];
        sb2[k] = bb * a[OUT_DIM + k];
    }
    __syncthreads();
    if (k == 0) {
        float t1 = 0.f, t2 = 0.f;
        for (int j = 0; j < OUT_DIM; j++) { t1 += sb1[j]; t2 += sb2[j]; }
        g_c1 = t1; g_c2 = t2;
    }
}

// ---------------- K_init: reset slot map & counters ----------------
__global__ void k_init() {
    int i = blockIdx.x * blockDim.x + threadIdx.x;
    if (i < N_NODES) g_slot[i] = 0x7fffffff;
    if (i < BATCH)   g_cnt[i] = 0;
}

// ---------------- K_mark: node -> min batch position ----------------
__global__ void k_mark(const void* __restrict__ bidx) {
    int i = blockIdx.x * blockDim.x + threadIdx.x;
    if (i >= BATCH) return;
    int node = load_idx(bidx, i, g_is64);
    atomicMin(&g_slot[node], i);
}

// ---------------- K_ssrc: per batch position, s_src = feats[node].v1 + c1 ----------------
__global__ __launch_bounds__(256) void k_ssrc(const float* __restrict__ feats,
                                              const void* __restrict__ bidx) {
    int gw   = (blockIdx.x * blockDim.x + threadIdx.x) >> 5;
    int lane = threadIdx.x & 31;
    if (gw >= BATCH) return;
    int node = load_idx(bidx, gw, g_is64);
    const float4* row = (const float4*)(feats + (size_t)node * IN_DIM);
    float s = 0.f;
#pragma unroll
    for (int t = 0; t < 2; t++) {
        float4 f = row[lane * 2 + t];
        int base = lane * 8 + t * 4;
        s += f.x * g_v1[base] + f.y * g_v1[base + 1] + f.z * g_v1[base + 2] + f.w * g_v1[base + 3];
    }
#pragma unroll
    for (int off = 16; off; off >>= 1) s += __shfl_xor_sync(0xffffffffu, s, off);
    if (lane == 0) g_ssrc[gw] = s + g_c1;
}

// ---------------- K_edge: filter edges by marked r, bucket c by slot ----------------
__global__ __launch_bounds__(256) void k_edge(const void* __restrict__ rp,
                                              const void* __restrict__ cp) {
    int e = blockIdx.x * blockDim.x + threadIdx.x;
    if (e >= N_EDGES) return;
    int is64 = g_is64;
    int r = load_idx(rp, e, is64);
    int slot = g_slot[r];
    if (slot >= BATCH) return;            // unmarked destination: ~92% of edges exit here
    int c = load_idx(cp, e, is64);
    int pos = atomicAdd(&g_cnt[slot], 1);
    if (pos < CAP) g_gc[slot * CAP + pos] = c;
}

// ---------------- K_agg: warp per slot; inline s_dst + softmax weight + aggregate ----------------
__global__ __launch_bounds__(256) void k_agg(const float* __restrict__ feats) {
    int gw   = (blockIdx.x * blockDim.x + threadIdx.x) >> 5;
    int lane = threadIdx.x & 31;
    if (gw >= BATCH) return;
    int n = g_cnt[gw];
    if (n > CAP) n = CAP;
    float ssrc = g_ssrc[gw] + g_c2;       // fold c2 in once
    float v2a[8];
#pragma unroll
    for (int t = 0; t < 8; t++) v2a[t] = g_v2[lane * 8 + t];

    float acc[8] = {0.f, 0.f, 0.f, 0.f, 0.f, 0.f, 0.f, 0.f};
    float dsum = 0.f;
    const int* gc = &g_gc[gw * CAP];

    float4 f0 = make_float4(0.f, 0.f, 0.f, 0.f), f1 = f0;
    if (n > 0) {
        int c0 = gc[0];
        const float4* row = (const float4*)(feats + (size_t)c0 * IN_DIM);
        f0 = row[lane * 2];
        f1 = row[lane * 2 + 1];
    }
    for (int i = 0; i < n; i++) {
        float4 n0 = f0, n1 = f1;          // prefetch next row to overlap DRAM latency
        if (i + 1 < n) {
            int cn = gc[i + 1];
            const float4* row = (const float4*)(feats + (size_t)cn * IN_DIM);
            n0 = row[lane * 2];
            n1 = row[lane * 2 + 1];
        }
        // s_dst from the row we already loaded
        float sd = f0.x * v2a[0] + f0.y * v2a[1] + f0.z * v2a[2] + f0.w * v2a[3]
                 + f1.x * v2a[4] + f1.y * v2a[5] + f1.z * v2a[6] + f1.w * v2a[7];
#pragma unroll
        for (int off = 16; off; off >>= 1) sd += __shfl_xor_sync(0xffffffffu, sd, off);
        float x = ssrc + sd;
        float w = expf(x > 0.f ? x : SLOPE * x);
        dsum += w;
        acc[0] += w * f0.x; acc[1] += w * f0.y; acc[2] += w * f0.z; acc[3] += w * f0.w;
        acc[4] += w * f1.x; acc[5] += w * f1.y; acc[6] += w * f1.z; acc[7] += w * f1.w;
        f0 = n0; f1 = n1;
    }
    float4* out = (float4*)&g_agg[gw * IN_DIM + lane * 8];
    out[0] = make_float4(acc[0], acc[1], acc[2], acc[3]);
    out[1] = make_float4(acc[4], acc[5], acc[6], acc[7]);
    if (lane == 0) g_denom[gw] = dsum;
}

// ---------------- K_gemm: [8192x256] @ [256x128] + epilogue (denom*b, /denom) ----------------
#define GBM 64
#define GBK 32
__global__ __launch_bounds__(256) void k_gemm(const float* __restrict__ W,
                                              const float* __restrict__ bvec) {
    __shared__ float As[GBK][GBM + 1];    // A transposed, padded vs bank conflicts
    __shared__ float Bs[GBK][OUT_DIM];
    int tid = threadIdx.x;
    int ty = tid >> 5;                    // 0..7  -> row group
    int tx = tid & 31;                    // 0..31 -> col group
    int rowBase = blockIdx.x * GBM;
    float acc[8][4] = {};

    for (int k0 = 0; k0 < IN_DIM; k0 += GBK) {
#pragma unroll
        for (int i = 0; i < 2; i++) {     // A tile: 64x32 floats = 512 float4
            int f = tid + i * 256;
            int r = f >> 3;
            int kk = (f & 7) << 2;
            float4 v = *(const float4*)&g_agg[(size_t)(rowBase + r) * IN_DIM + k0 + kk];
            As[kk][r] = v.x; As[kk + 1][r] = v.y; As[kk + 2][r] = v.z; As[kk + 3][r] = v.w;
        }
#pragma unroll
        for (int i = 0; i < 4; i++) {     // B tile: 32x128 floats = 1024 float4
            int f = tid + i * 256;
            int kk = f >> 5;
            int cc = (f & 31) << 2;
            *(float4*)&Bs[kk][cc] = *(const float4*)&W[(size_t)(k0 + kk) * OUT_DIM + cc];
        }
        __syncthreads();
#pragma unroll
        for (int k = 0; k < GBK; k++) {
            float a0[8];
#pragma unroll
            for (int r = 0; r < 8; r++) a0[r] = As[k][ty * 8 + r];   // warp-broadcast
            float4 bb = *(const float4*)&Bs[k][tx * 4];
#pragma unroll
            for (int r = 0; r < 8; r++) {
                acc[r][0] += a0[r] * bb.x;
                acc[r][1] += a0[r] * bb.y;
                acc[r][2] += a0[r] * bb.z;
                acc[r][3] += a0[r] * bb.w;
            }
        }
        __syncthreads();
    }

    float4 bv = *(const float4*)&bvec[tx * 4];
#pragma unroll
    for (int r = 0; r < 8; r++) {
        int row = rowBase + ty * 8 + r;
        float dn = g_denom[row];
        float inv = 1.0f / (dn + EPS);
        float4 o;
        o.x = (acc[r][0] + dn * bv.x) * inv;
        o.y = (acc[r][1] + dn * bv.y) * inv;
        o.z = (acc[r][2] + dn * bv.z) * inv;
        o.w = (acc[r][3] + dn * bv.w) * inv;
        *(float4*)&g_outrow[(size_t)row * OUT_DIM + tx * 4] = o;
    }
}

// ---------------- K_out: out[i] = outrow[slot[batch_idx[i]]] ----------------
__global__ __launch_bounds__(256) void k_out(const void* __restrict__ bidx,
                                             float* __restrict__ out) {
    int gw   = (blockIdx.x * blockDim.x + threadIdx.x) >> 5;
    int lane = threadIdx.x & 31;
    if (gw >= BATCH) return;
    int node = load_idx(bidx, gw, g_is64);
    int slot = g_slot[node];              // representative slot (handles duplicates)
    float4 v = *(const float4*)&g_outrow[(size_t)slot * OUT_DIM + lane * 4];
    *(float4*)&out[(size_t)gw * OUT_DIM + lane * 4] = v;
}

// ---------------- launch ----------------
extern "C" void kernel_launch(void* const* d_in, const int* in_sizes, int n_in,
                              void* d_out, int out_size) {
    (void)in_sizes; (void)n_in; (void)out_size;
    const float* feats = (const float*)d_in[0];
    const float* W     = (const float*)d_in[1];
    const float* b     = (const float*)d_in[2];
    const float* a     = (const float*)d_in[3];
    const void*  r     = d_in[4];
    const void*  c     = d_in[5];
    const void*  bidx  = d_in[6];
    float* out = (float*)d_out;

    k_detect<<<1, 1>>>(r);
    k_prep<<<1, 256>>>(W, b, a);
    k_init<<<(N_NODES + 255) / 256, 256>>>();
    k_mark<<<(BATCH + 255) / 256, 256>>>(bidx);
    k_ssrc<<<BATCH / 8, 256>>>(feats, bidx);
    k_edge<<<N_EDGES / 256, 256>>>(r, c);
    k_agg<<<BATCH / 8, 256>>>(feats);
    k_gemm<<<BATCH / GBM, 256>>>(W, b);
    k_out<<<BATCH / 8, 256>>>(bidx, out);
}

// round 2
// speedup vs baseline: 1.0980x; 1.0980x over previous
#include <cuda_runtime.h>

#define N_NODES 100000
#define N_EDGES 1600000
#define IN_DIM  256
#define OUT_DIM 128
#define BATCH   8192
#define CAP     192
#define SLOPE   0.1f
#define EPS     1e-8f

#define NB_INIT 391   // ceil(100000/256)

// ---------------- static device scratch (no runtime allocation) ----------------
__device__ int   g_is64;                 // 1 if index arrays are int64, 0 if int32
__device__ float g_v1[IN_DIM];           // W @ a[:128]
__device__ float g_v2[IN_DIM];           // W @ a[128:]
__device__ float g_c1, g_c2;             // b.a[:128], b.a[128:]
__device__ int   g_slot[N_NODES];        // node -> representative batch slot (INT_MAX if unmarked)
__device__ int   g_cnt[BATCH];           // edges bucketed per slot
__device__ float g_ssrc[BATCH];          // s_src per batch position (incl. c1)
__device__ int   g_gc[BATCH * CAP];      // bucketed c-endpoints per slot
__device__ __align__(16) float g_agg[BATCH * IN_DIM];     // sum_e w_e * feats[c_e]
__device__ float g_denom[BATCH];
__device__ __align__(16) float g_outrow[BATCH * OUT_DIM]; // per-slot final rows

__device__ __forceinline__ int load_idx(const void* p, int i, int is64) {
    if (is64) return (int)((const long long*)p)[i];
    return ((const int*)p)[i];
}

// ---------------- K_setup: init slot map + counters, parallel dtype detect, prep vectors ----------------
// blocks [0, NB_INIT): init   | block NB_INIT: prep (v1,v2,c1,c2) | block NB_INIT+1: detect
__global__ __launch_bounds__(256) void k_setup(const float* __restrict__ W,
                                               const float* __restrict__ b,
                                               const float* __restrict__ a,
                                               const void* __restrict__ rp) {
    int blk = blockIdx.x;
    int t = threadIdx.x;

    if (blk < NB_INIT) {
        int i = blk * 256 + t;
        if (i < N_NODES) g_slot[i] = 0x7fffffff;
        if (i < BATCH)   g_cnt[i] = 0;
        return;
    }

    if (blk == NB_INIT) {
        // prep: v1 = W@a1, v2 = W@a2 (one thread per K row), c1 = b.a1, c2 = b.a2
        const float* wrow = W + t * OUT_DIM;
        float s1 = 0.f, s2 = 0.f;
#pragma unroll 4
        for (int j = 0; j < OUT_DIM; j++) {
            float w = wrow[j];
            s1 += w * a[j];
            s2 += w * a[OUT_DIM + j];
        }
        g_v1[t] = s1;
        g_v2[t] = s2;

        __shared__ float sb1[OUT_DIM], sb2[OUT_DIM];
        if (t < OUT_DIM) {
            float bb = b[t];
            sb1[t] = bb * a[t];
            sb2[t] = bb * a[OUT_DIM + t];
        }
        __syncthreads();
        if (t == 0) {
            float t1 = 0.f, t2 = 0.f;
            for (int j = 0; j < OUT_DIM; j++) { t1 += sb1[j]; t2 += sb2[j]; }
            g_c1 = t1; g_c2 = t2;
        }
        return;
    }

    // detect: interpret r as int64; 32 lanes x 2 samples in parallel (not serial!)
    if (t < 32) {
        const long long* r64 = (const long long*)rp;
        const long long stride = (N_EDGES / 2) / 64;   // 12500 (safe for both dtypes)
        long long v0 = r64[(long long)t * stride];
        long long v1 = r64[(long long)(t + 32) * stride];
        int ok = (v0 >= 0 && v0 < N_NODES) && (v1 >= 0 && v1 < N_NODES);
        int all = __all_sync(0xffffffffu, ok);
        if (t == 0) g_is64 = all;   // int32 pairs read as huge int64s; P(false pos) ~ (1e-5)^64
    }
}

// ---------------- K_mark_ssrc: warp per batch position; atomicMin slot + s_src dot ----------------
__global__ __launch_bounds__(256) void k_mark_ssrc(const float* __restrict__ feats,
                                                   const void* __restrict__ bidx) {
    int gw   = (blockIdx.x * blockDim.x + threadIdx.x) >> 5;
    int lane = threadIdx.x & 31;
    if (gw >= BATCH) return;
    int node = load_idx(bidx, gw, g_is64);
    if (lane == 0) atomicMin(&g_slot[node], gw);

    const float4* row = (const float4*)(feats + (size_t)node * IN_DIM);
    float s = 0.f;
#pragma unroll
    for (int tt = 0; tt < 2; tt++) {
        float4 f = row[lane * 2 + tt];
        int base = lane * 8 + tt * 4;
        s += f.x * g_v1[base] + f.y * g_v1[base + 1] + f.z * g_v1[base + 2] + f.w * g_v1[base + 3];
    }
#pragma unroll
    for (int off = 16; off; off >>= 1) s += __shfl_xor_sync(0xffffffffu, s, off);
    if (lane == 0) g_ssrc[gw] = s + g_c1;
}

// ---------------- K_edge: filter edges by marked r, bucket c by slot (2 edges / thread) ----------------
__global__ __launch_bounds__(256) void k_edge(const void* __restrict__ rp,
                                              const void* __restrict__ cp) {
    int base = (blockIdx.x * blockDim.x + threadIdx.x) * 2;
    if (base >= N_EDGES) return;
    int is64 = g_is64;
    int r0, r1;
    if (is64) {
        longlong2 rr = ((const longlong2*)rp)[base >> 1];
        r0 = (int)rr.x; r1 = (int)rr.y;
    } else {
        int2 rr = ((const int2*)rp)[base >> 1];
        r0 = rr.x; r1 = rr.y;
    }
    int s0 = g_slot[r0];
    int s1 = g_slot[r1];
    if (s0 < BATCH) {
        int c = load_idx(cp, base, is64);
        int pos = atomicAdd(&g_cnt[s0], 1);
        if (pos < CAP) g_gc[s0 * CAP + pos] = c;
    }
    if (s1 < BATCH) {
        int c = load_idx(cp, base + 1, is64);
        int pos = atomicAdd(&g_cnt[s1], 1);
        if (pos < CAP) g_gc[s1 * CAP + pos] = c;
    }
}

// ---------------- K_agg: warp per slot; inline s_dst + softmax weight + aggregate ----------------
__global__ __launch_bounds__(256) void k_agg(const float* __restrict__ feats) {
    int gw   = (blockIdx.x * blockDim.x + threadIdx.x) >> 5;
    int lane = threadIdx.x & 31;
    if (gw >= BATCH) return;
    int n = g_cnt[gw];
    if (n > CAP) n = CAP;
    float ssrc = g_ssrc[gw] + g_c2;       // fold c2 in once
    float v2a[8];
#pragma unroll
    for (int tt = 0; tt < 8; tt++) v2a[tt] = g_v2[lane * 8 + tt];

    float acc[8] = {0.f, 0.f, 0.f, 0.f, 0.f, 0.f, 0.f, 0.f};
    float dsum = 0.f;
    const int* gc = &g_gc[gw * CAP];

    float4 f0 = make_float4(0.f, 0.f, 0.f, 0.f), f1 = f0;
    if (n > 0) {
        int c0 = gc[0];
        const float4* row = (const float4*)(feats + (size_t)c0 * IN_DIM);
        f0 = row[lane * 2];
        f1 = row[lane * 2 + 1];
    }
    for (int i = 0; i < n; i++) {
        float4 n0 = f0, n1 = f1;          // prefetch next row to overlap DRAM latency
        if (i + 1 < n) {
            int cn = gc[i + 1];
            const float4* row = (const float4*)(feats + (size_t)cn * IN_DIM);
            n0 = row[lane * 2];
            n1 = row[lane * 2 + 1];
        }
        // s_dst from the row we already loaded
        float sd = f0.x * v2a[0] + f0.y * v2a[1] + f0.z * v2a[2] + f0.w * v2a[3]
                 + f1.x * v2a[4] + f1.y * v2a[5] + f1.z * v2a[6] + f1.w * v2a[7];
#pragma unroll
        for (int off = 16; off; off >>= 1) sd += __shfl_xor_sync(0xffffffffu, sd, off);
        float x = ssrc + sd;
        float w = __expf(x > 0.f ? x : SLOPE * x);
        dsum += w;
        acc[0] += w * f0.x; acc[1] += w * f0.y; acc[2] += w * f0.z; acc[3] += w * f0.w;
        acc[4] += w * f1.x; acc[5] += w * f1.y; acc[6] += w * f1.z; acc[7] += w * f1.w;
        f0 = n0; f1 = n1;
    }
    float4* out = (float4*)&g_agg[gw * IN_DIM + lane * 8];
    out[0] = make_float4(acc[0], acc[1], acc[2], acc[3]);
    out[1] = make_float4(acc[4], acc[5], acc[6], acc[7]);
    if (lane == 0) g_denom[gw] = dsum;
}

// ---------------- K_gemm: [8192x256] @ [256x128] + epilogue (denom*b, /denom) ----------------
#define GBM 64
#define GBK 32
__global__ __launch_bounds__(256) void k_gemm(const float* __restrict__ W,
                                              const float* __restrict__ bvec) {
    __shared__ float As[GBK][GBM + 1];    // A transposed, padded vs bank conflicts
    __shared__ float Bs[GBK][OUT_DIM];
    int tid = threadIdx.x;
    int ty = tid >> 5;                    // 0..7  -> row group
    int tx = tid & 31;                    // 0..31 -> col group
    int rowBase = blockIdx.x * GBM;
    float acc[8][4] = {};

    for (int k0 = 0; k0 < IN_DIM; k0 += GBK) {
#pragma unroll
        for (int i = 0; i < 2; i++) {     // A tile: 64x32 floats = 512 float4
            int f = tid + i * 256;
            int r = f >> 3;
            int kk = (f & 7) << 2;
            float4 v = *(const float4*)&g_agg[(size_t)(rowBase + r) * IN_DIM + k0 + kk];
            As[kk][r] = v.x; As[kk + 1][r] = v.y; As[kk + 2][r] = v.z; As[kk + 3][r] = v.w;
        }
#pragma unroll
        for (int i = 0; i < 4; i++) {     // B tile: 32x128 floats = 1024 float4
            int f = tid + i * 256;
            int kk = f >> 5;
            int cc = (f & 31) << 2;
            *(float4*)&Bs[kk][cc] = *(const float4*)&W[(size_t)(k0 + kk) * OUT_DIM + cc];
        }
        __syncthreads();
#pragma unroll
        for (int k = 0; k < GBK; k++) {
            float a0[8];
#pragma unroll
            for (int r = 0; r < 8; r++) a0[r] = As[k][ty * 8 + r];   // warp-broadcast
            float4 bb = *(const float4*)&Bs[k][tx * 4];
#pragma unroll
            for (int r = 0; r < 8; r++) {
                acc[r][0] += a0[r] * bb.x;
                acc[r][1] += a0[r] * bb.y;
                acc[r][2] += a0[r] * bb.z;
                acc[r][3] += a0[r] * bb.w;
            }
        }
        __syncthreads();
    }

    float4 bv = *(const float4*)&bvec[tx * 4];
#pragma unroll
    for (int r = 0; r < 8; r++) {
        int row = rowBase + ty * 8 + r;
        float dn = g_denom[row];
        float inv = 1.0f / (dn + EPS);
        float4 o;
        o.x = (acc[r][0] + dn * bv.x) * inv;
        o.y = (acc[r][1] + dn * bv.y) * inv;
        o.z = (acc[r][2] + dn * bv.z) * inv;
        o.w = (acc[r][3] + dn * bv.w) * inv;
        *(float4*)&g_outrow[(size_t)row * OUT_DIM + tx * 4] = o;
    }
}

// ---------------- K_out: out[i] = outrow[slot[batch_idx[i]]] ----------------
__global__ __launch_bounds__(256) void k_out(const void* __restrict__ bidx,
                                             float* __restrict__ out) {
    int gw   = (blockIdx.x * blockDim.x + threadIdx.x) >> 5;
    int lane = threadIdx.x & 31;
    if (gw >= BATCH) return;
    int node = load_idx(bidx, gw, g_is64);
    int slot = g_slot[node];              // representative slot (handles duplicates)
    float4 v = *(const float4*)&g_outrow[(size_t)slot * OUT_DIM + lane * 4];
    *(float4*)&out[(size_t)gw * OUT_DIM + lane * 4] = v;
}

// ---------------- launch ----------------
extern "C" void kernel_launch(void* const* d_in, const int* in_sizes, int n_in,
                              void* d_out, int out_size) {
    (void)in_sizes; (void)n_in; (void)out_size;
    const float* feats = (const float*)d_in[0];
    const float* W     = (const float*)d_in[1];
    const float* b     = (const float*)d_in[2];
    const float* a     = (const float*)d_in[3];
    const void*  r     = d_in[4];
    const void*  c     = d_in[5];
    const void*  bidx  = d_in[6];
    float* out = (float*)d_out;

    k_setup<<<NB_INIT + 2, 256>>>(W, b, a, r);
    k_mark_ssrc<<<BATCH / 8, 256>>>(feats, bidx);
    k_edge<<<N_EDGES / 512, 256>>>(r, c);
    k_agg<<<BATCH / 8, 256>>>(feats);
    k_gemm<<<BATCH / GBM, 256>>>(W, b);
    k_out<<<BATCH / 8, 256>>>(bidx, out);
}

// round 4
// speedup vs baseline: 1.0984x; 1.0004x over previous
#include <cuda_runtime.h>

#define N_NODES 100000
#define N_EDGES 1600000
#define IN_DIM  256
#define OUT_DIM 128
#define BATCH   8192
#define CAP     192
#define SLOPE   0.1f
#define EPS     1e-8f

#define NB_INIT 391   // ceil(100000/256)

// ---------------- static device scratch (no runtime allocation) ----------------
__device__ int   g_is64;                 // 1 if index arrays are int64, 0 if int32
__device__ float g_v1[IN_DIM];           // W @ a[:128]
__device__ float g_v2[IN_DIM];           // W @ a[128:]
__device__ float g_c1, g_c2;             // b.a[:128], b.a[128:]
__device__ int   g_slot[N_NODES];        // node -> representative batch slot (INT_MAX if unmarked)
__device__ int   g_cnt[BATCH];           // edges bucketed per slot
__device__ float g_ssrc[BATCH];          // s_src per batch position (incl. c1)
__device__ int   g_gc[BATCH * CAP];      // bucketed c-endpoints per slot
__device__ __align__(16) float g_agg[BATCH * IN_DIM];     // sum_e w_e * feats[c_e]
__device__ float g_denom[BATCH];

__device__ __forceinline__ int load_idx(const void* p, int i, int is64) {
    if (is64) return (int)((const long long*)p)[i];
    return ((const int*)p)[i];
}

// ---------------- K_setup: init slot map + counters, parallel dtype detect, prep vectors ----------------
__global__ __launch_bounds__(256) void k_setup(const float* __restrict__ W,
                                               const float* __restrict__ b,
                                               const float* __restrict__ a,
                                               const void* __restrict__ rp) {
    int blk = blockIdx.x;
    int t = threadIdx.x;

    if (blk < NB_INIT) {
        int i = blk * 256 + t;
        if (i < N_NODES) g_slot[i] = 0x7fffffff;
        if (i < BATCH)   g_cnt[i] = 0;
        return;
    }

    if (blk == NB_INIT) {
        // prep: v1 = W@a1, v2 = W@a2 (one thread per K row), c1 = b.a1, c2 = b.a2
        const float* wrow = W + t * OUT_DIM;
        float s1 = 0.f, s2 = 0.f;
#pragma unroll 4
        for (int j = 0; j < OUT_DIM; j++) {
            float w = wrow[j];
            s1 += w * a[j];
            s2 += w * a[OUT_DIM + j];
        }
        g_v1[t] = s1;
        g_v2[t] = s2;

        __shared__ float sb1[OUT_DIM], sb2[OUT_DIM];
        if (t < OUT_DIM) {
            float bb = b[t];
            sb1[t] = bb * a[t];
            sb2[t] = bb * a[OUT_DIM + t];
        }
        __syncthreads();
        if (t == 0) {
            float t1 = 0.f, t2 = 0.f;
            for (int j = 0; j < OUT_DIM; j++) { t1 += sb1[j]; t2 += sb2[j]; }
            g_c1 = t1; g_c2 = t2;
        }
        return;
    }

    // detect: 32 lanes x 2 parallel int64 samples
    if (t < 32) {
        const long long* r64 = (const long long*)rp;
        const long long stride = (N_EDGES / 2) / 64;   // 12500 (safe for both dtypes)
        long long v0 = r64[(long long)t * stride];
        long long v1 = r64[(long long)(t + 32) * stride];
        int ok = (v0 >= 0 && v0 < N_NODES) && (v1 >= 0 && v1 < N_NODES);
        int all = __all_sync(0xffffffffu, ok);
        if (t == 0) g_is64 = all;
    }
}

// ---------------- K_mark_ssrc: warp per batch position; atomicMin slot + s_src dot ----------------
__global__ __launch_bounds__(256) void k_mark_ssrc(const float* __restrict__ feats,
                                                   const void* __restrict__ bidx) {
    int gw   = (blockIdx.x * blockDim.x + threadIdx.x) >> 5;
    int lane = threadIdx.x & 31;
    if (gw >= BATCH) return;
    int node = load_idx(bidx, gw, g_is64);
    if (lane == 0) atomicMin(&g_slot[node], gw);

    const float4* row = (const float4*)(feats + (size_t)node * IN_DIM);
    float4 fA = row[lane * 2];
    float4 fB = row[lane * 2 + 1];
    int base = lane * 8;
    float s = fA.x * g_v1[base]     + fA.y * g_v1[base + 1] + fA.z * g_v1[base + 2] + fA.w * g_v1[base + 3]
            + fB.x * g_v1[base + 4] + fB.y * g_v1[base + 5] + fB.z * g_v1[base + 6] + fB.w * g_v1[base + 7];
#pragma unroll
    for (int off = 16; off; off >>= 1) s += __shfl_xor_sync(0xffffffffu, s, off);
    if (lane == 0) g_ssrc[gw] = s + g_c1;
}

// ---------------- K_edge: filter edges by marked r, bucket c by slot (4 edges / thread) ----------------
__global__ __launch_bounds__(256) void k_edge(const void* __restrict__ rp,
                                              const void* __restrict__ cp) {
    int base = (blockIdx.x * blockDim.x + threadIdx.x) * 4;
    if (base >= N_EDGES) return;     // N_EDGES % 4 == 0, so full vector or nothing
    int is64 = g_is64;
    int r[4];
    if (is64) {
        longlong4 rr = ((const longlong4*)rp)[base >> 2];
        r[0] = (int)rr.x; r[1] = (int)rr.y; r[2] = (int)rr.z; r[3] = (int)rr.w;
    } else {
        int4 rr = ((const int4*)rp)[base >> 2];
        r[0] = rr.x; r[1] = rr.y; r[2] = rr.z; r[3] = rr.w;
    }
    int s[4];
#pragma unroll
    for (int k = 0; k < 4; k++) s[k] = g_slot[r[k]];
#pragma unroll
    for (int k = 0; k < 4; k++) {
        if (s[k] < BATCH) {
            int c = load_idx(cp, base + k, is64);
            int pos = atomicAdd(&g_cnt[s[k]], 1);
            if (pos < CAP) g_gc[s[k] * CAP + pos] = c;
        }
    }
}

// ---------------- K_agg: warp per slot; 2-edge ILP pipeline ----------------
__global__ __launch_bounds__(128) void k_agg(const float* __restrict__ feats) {
    int gw   = (blockIdx.x * blockDim.x + threadIdx.x) >> 5;
    int lane = threadIdx.x & 31;
    if (gw >= BATCH) return;
    int n = g_cnt[gw];
    if (n > CAP) n = CAP;
    if (n == 0) {
        float4 z = make_float4(0.f, 0.f, 0.f, 0.f);
        float4* outz = (float4*)&g_agg[gw * IN_DIM + lane * 8];
        outz[0] = z; outz[1] = z;
        if (lane == 0) g_denom[gw] = 0.f;
        return;
    }
    float ssrc = g_ssrc[gw] + g_c2;
    float v2a[8];
#pragma unroll
    for (int tt = 0; tt < 8; tt++) v2a[tt] = g_v2[lane * 8 + tt];

    float acc[8] = {};
    float dsum = 0.f;
    const int* gc = &g_gc[gw * CAP];

    // pipeline registers: current pair (a,b) and next pair
    float4 a0, a1, b0, b1;
    {
        int ca = gc[0];
        int cb = gc[(1 < n) ? 1 : 0];
        const float4* ra = (const float4*)(feats + (size_t)ca * IN_DIM);
        const float4* rb = (const float4*)(feats + (size_t)cb * IN_DIM);
        a0 = ra[lane * 2]; a1 = ra[lane * 2 + 1];
        b0 = rb[lane * 2]; b1 = rb[lane * 2 + 1];
    }

    for (int i = 0; i < n; i += 2) {
        // prefetch next pair (clamped indices; results discarded past end)
        float4 na0 = a0, na1 = a1, nb0 = b0, nb1 = b1;
        if (i + 2 < n) {
            int ca = gc[i + 2];
            int cb = gc[(i + 3 < n) ? (i + 3) : (i + 2)];
            const float4* ra = (const float4*)(feats + (size_t)ca * IN_DIM);
            const float4* rb = (const float4*)(feats + (size_t)cb * IN_DIM);
            na0 = ra[lane * 2]; na1 = ra[lane * 2 + 1];
            nb0 = rb[lane * 2]; nb1 = rb[lane * 2 + 1];
        }

        // two independent dot-products, interleaved shuffle chains
        float sa = a0.x * v2a[0] + a0.y * v2a[1] + a0.z * v2a[2] + a0.w * v2a[3]
                 + a1.x * v2a[4] + a1.y * v2a[5] + a1.z * v2a[6] + a1.w * v2a[7];
        float sb = b0.x * v2a[0] + b0.y * v2a[1] + b0.z * v2a[2] + b0.w * v2a[3]
                 + b1.x * v2a[4] + b1.y * v2a[5] + b1.z * v2a[6] + b1.w * v2a[7];
#pragma unroll
        for (int off = 16; off; off >>= 1) {
            sa += __shfl_xor_sync(0xffffffffu, sa, off);
            sb += __shfl_xor_sync(0xffffffffu, sb, off);
        }
        float xa = ssrc + sa;
        float xb = ssrc + sb;
        float wa = __expf(xa > 0.f ? xa : SLOPE * xa);
        float wb = __expf(xb > 0.f ? xb : SLOPE * xb);
        if (i + 1 >= n) wb = 0.f;          // odd tail: second edge invalid
        dsum += wa + wb;
        acc[0] += wa * a0.x + wb * b0.x;
        acc[1] += wa * a0.y + wb * b0.y;
        acc[2] += wa * a0.z + wb * b0.z;
        acc[3] += wa * a0.w + wb * b0.w;
        acc[4] += wa * a1.x + wb * b1.x;
        acc[5] += wa * a1.y + wb * b1.y;
        acc[6] += wa * a1.z + wb * b1.z;
        acc[7] += wa * a1.w + wb * b1.w;

        a0 = na0; a1 = na1; b0 = nb0; b1 = nb1;
    }
    float4* out = (float4*)&g_agg[gw * IN_DIM + lane * 8];
    out[0] = make_float4(acc[0], acc[1], acc[2], acc[3]);
    out[1] = make_float4(acc[4], acc[5], acc[6], acc[7]);
    if (lane == 0) g_denom[gw] = dsum;
}

// ---------------- K_gemm: [8192x256]@[256x128] + epilogue, writes d_out directly ----------------
#define GBM 64
#define GBK 32
__global__ __launch_bounds__(256) void k_gemm(const float* __restrict__ W,
                                              const float* __restrict__ bvec,
                                              float* __restrict__ out) {
    __shared__ float As[GBK][GBM + 1];
    __shared__ float Bs[GBK][OUT_DIM];
    int tid = threadIdx.x;
    int ty = tid >> 5;
    int tx = tid & 31;
    int rowBase = blockIdx.x * GBM;
    float acc[8][4] = {};

    for (int k0 = 0; k0 < IN_DIM; k0 += GBK) {
#pragma unroll
        for (int i = 0; i < 2; i++) {
            int f = tid + i * 256;
            int r = f >> 3;
            int kk = (f & 7) << 2;
            float4 v = *(const float4*)&g_agg[(size_t)(rowBase + r) * IN_DIM + k0 + kk];
            As[kk][r] = v.x; As[kk + 1][r] = v.y; As[kk + 2][r] = v.z; As[kk + 3][r] = v.w;
        }
#pragma unroll
        for (int i = 0; i < 4; i++) {
            int f = tid + i * 256;
            int kk = f >> 5;
            int cc = (f & 31) << 2;
            *(float4*)&Bs[kk][cc] = *(const float4*)&W[(size_t)(k0 + kk) * OUT_DIM + cc];
        }
        __syncthreads();
#pragma unroll
        for (int k = 0; k < GBK; k++) {
            float a0[8];
#pragma unroll
            for (int r = 0; r < 8; r++) a0[r] = As[k][ty * 8 + r];
            float4 bb = *(const float4*)&Bs[k][tx * 4];
#pragma unroll
            for (int r = 0; r < 8; r++) {
                acc[r][0] += a0[r] * bb.x;
                acc[r][1] += a0[r] * bb.y;
                acc[r][2] += a0[r] * bb.z;
                acc[r][3] += a0[r] * bb.w;
            }
        }
        __syncthreads();
    }

    float4 bv = *(const float4*)&bvec[tx * 4];
#pragma unroll
    for (int r = 0; r < 8; r++) {
        int row = rowBase + ty * 8 + r;
        float dn = g_denom[row];
        float inv = 1.0f / (dn + EPS);
        float4 o;
        o.x = (acc[r][0] + dn * bv.x) * inv;
        o.y = (acc[r][1] + dn * bv.y) * inv;
        o.z = (acc[r][2] + dn * bv.z) * inv;
        o.w = (acc[r][3] + dn * bv.w) * inv;
        *(float4*)&out[(size_t)row * OUT_DIM + tx * 4] = o;
    }
}

// ---------------- K_fix: copy rows for duplicate batch positions (slot != i) ----------------
__global__ __launch_bounds__(256) void k_fix(const void* __restrict__ bidx,
                                             float* __restrict__ out) {
    int gw   = (blockIdx.x * blockDim.x + threadIdx.x) >> 5;
    int lane = threadIdx.x & 31;
    if (gw >= BATCH) return;
    int node = load_idx(bidx, gw, g_is64);
    int slot = g_slot[node];
    if (slot == gw) return;               // representative: k_gemm already wrote the row
    float4 v = *(const float4*)&out[(size_t)slot * OUT_DIM + lane * 4];
    *(float4*)&out[(size_t)gw * OUT_DIM + lane * 4] = v;
}

// ---------------- launch ----------------
extern "C" void kernel_launch(void* const* d_in, const int* in_sizes, int n_in,
                              void* d_out, int out_size) {
    (void)in_sizes; (void)n_in; (void)out_size;
    const float* feats = (const float*)d_in[0];
    const float* W     = (const float*)d_in[1];
    const float* b     = (const float*)d_in[2];
    const float* a     = (const float*)d_in[3];
    const void*  r     = d_in[4];
    const void*  c     = d_in[5];
    const void*  bidx  = d_in[6];
    float* out = (float*)d_out;

    k_setup<<<NB_INIT + 2, 256>>>(W, b, a, r);
    k_mark_ssrc<<<BATCH / 8, 256>>>(feats, bidx);
    k_edge<<<(N_EDGES / 4 + 255) / 256, 256>>>(r, c);   // 1563 blocks: FULL edge coverage
    k_agg<<<BATCH / 4, 128>>>(feats);
    k_gemm<<<BATCH / GBM, 256>>>(W, b, out);
    k_fix<<<BATCH / 8, 256>>>(bidx, out);
}